// round 15
// baseline (speedup 1.0000x reference)
#include <cuda_runtime.h>
#include <math.h>

// ---------------- problem constants ----------------
#define NB     8
#define CIN    512
#define HH     64
#define WW     64
#define NPOS   4096              // 64*64
#define NA     9
#define NANCH  36864             // 4096*9 = 9 blocks of 4096
#define NSORT  65536             // per-image key stride (only blocks 0..8 used)
#define NPRE   3000
#define NPOST  600
#define WPR    47                // words per NMS mask row: ceil(3008/64)
#define NPAD   68                // padded row stride (272B = 16B-aligned rows)
#define XPLANE (NPAD*NPAD)       // 4624

// output layout (floats)
#define OFF_LOCS   ((size_t)0)
#define OFF_SCORES ((size_t)(NB*NANCH*4))                      // 1,179,648
#define OFF_ROIS   (OFF_SCORES + (size_t)(NB*NANCH*2))         // 1,769,472
#define OFF_RIDX   (OFF_ROIS + (size_t)(NB*NPOST*4))           // 1,788,672
#define OFF_ANCH   (OFF_RIDX + (size_t)(NB*NPOST))             // 1,793,472

// ---------------- static scratch ----------------
__device__ float               g_feat[(size_t)NB*CIN*NPOS];        // 64 MiB
__device__ float               g_xpad[(size_t)NB*CIN*XPLANE];      // 75 MiB padded input
__device__ float               g_wt[(size_t)CIN*9*CIN];            // transposed weights [ic*9+kk][oc]
__device__ float4              g_roi[(size_t)NB*NANCH];            // clipped rois
__device__ unsigned long long  g_keys[(size_t)NB*NSORT];           // sort keys
__device__ float4              g_topbox[(size_t)NB*3008];
__device__ unsigned long long  g_vmask[(size_t)NB*WPR];
__device__ unsigned long long  g_mask[(size_t)NB*NPRE*WPR];        // 9 MiB

// ---------------- packed f32x2 helpers ----------------
#define FMA2(d, a, b, c) \
    asm("fma.rn.f32x2 %0, %1, %2, %3;" : "=l"(d) : "l"(a), "l"(b), "l"(c))
#define ADD2(d, a, b) \
    asm("add.rn.f32x2 %0, %1, %2;" : "=l"(d) : "l"(a), "l"(b))
#define PACK2(d, f) \
    asm("mov.b64 %0, {%1, %1};" : "=l"(d) : "f"(f))
#define UNPACK2(lo, hi, v) \
    asm("mov.b64 {%0, %1}, %2;" : "=f"(lo), "=f"(hi) : "l"(v))

// ---------------- cp.async helpers ----------------
__device__ __forceinline__ unsigned int smem_u32(const void* p) {
    return (unsigned int)__cvta_generic_to_shared(p);
}
__device__ __forceinline__ void cpa16(unsigned int dst, const float* src) {
    asm volatile("cp.async.cg.shared.global [%0], [%1], 16;" :: "r"(dst), "l"(src));
}
#define CP_COMMIT() asm volatile("cp.async.commit_group;" ::: "memory")
#define CP_WAIT(n)  asm volatile("cp.async.wait_group %0;" :: "n"(n) : "memory")

// ---------------- prep: pad input, transpose weights ----------------
__global__ void pad_input(const float* __restrict__ x) {
    long long i = (long long)blockIdx.x * blockDim.x + threadIdx.x;
    if (i >= (long long)NB*CIN*XPLANE) return;
    int pos = (int)(i % XPLANE);
    long long plane = i / XPLANE;                  // n*CIN+ic
    int yy = pos / NPAD, xx = pos - yy*NPAD;
    float v = 0.f;
    if (yy >= 1 && yy <= 64 && xx >= 1 && xx <= 64)
        v = x[(plane << 12) + ((yy-1) << 6) + (xx-1)];
    g_xpad[i] = v;
}

__global__ void transpose_w(const float* __restrict__ w) {
    int i = blockIdx.x * blockDim.x + threadIdx.x;   // CIN*9*CIN = 2359296
    if (i >= CIN*9*CIN) return;
    int oc = i & 511;
    int row = i >> 9;                                 // ic*9+kk
    int ic = row / 9, kk = row - ic*9;
    g_wt[i] = w[((size_t)oc*CIN + ic)*9 + kk];
}

// ---------------- conv 3x3 + relu (8 px x 4 oc, 3-stage pipeline) ---------
#define XS_STRIDE 20           // padded row stride (16B alignment for LDS.128)
#define XS_IC     360          // 18*20
#define XS_ELEMS  2880         // 8*360
#define WS2       2304         // 72*32
#define CONV_SMEM (3*(XS_ELEMS+WS2)*4)
__global__ void __launch_bounds__(256, 2) conv3x3_relu(
    const float* __restrict__ bias)
{
    extern __shared__ float smem[];
    float* xs = smem;                       // [3][2880]
    float* ws = smem + 3*XS_ELEMS;          // [3][2304]
    const int tile = blockIdx.x;
    const int oc0  = blockIdx.y * 32;
    const int n    = blockIdx.z;
    const int tx0  = (tile & 3) * 16, ty0 = (tile >> 2) * 16;
    const int t    = threadIdx.x;
    const int ocg  = t >> 5;               // 0..7 -> 4 oc each
    const int pid  = t & 31;
    const int px0  = (pid & 1) * 8;        // 0,8
    const int py   = pid >> 1;             // 0..15

    const float* xbase = &g_xpad[((size_t)n*CIN) * XPLANE + (size_t)ty0*NPAD + tx0];
    const unsigned int xs_a = smem_u32(xs);
    const unsigned int ws_a = smem_u32(ws);

    unsigned long long acc2[16];           // [oc_pair 0..1][px 0..7]
#pragma unroll
    for (int i = 0; i < 16; ++i) acc2[i] = 0ull;

    auto issue = [&](int c, int b) {
        const int ic0 = c * 8;
        unsigned int xd = xs_a + (unsigned)b * (XS_ELEMS*4);
        const float* xsrc = xbase + (size_t)ic0 * XPLANE;
#pragma unroll 1
        for (int i = t; i < 720; i += 256) {
            int ic = i / 90, r = i - ic*90;
            int yy = r / 5, seg = r - yy*5;
            cpa16(xd + (unsigned)(ic*XS_IC + yy*XS_STRIDE + seg*4)*4,
                  xsrc + (size_t)ic*XPLANE + yy*NPAD + seg*4);
        }
        unsigned int wd = ws_a + (unsigned)b * (WS2*4);
        const float* wsrc = &g_wt[(size_t)(ic0*9) * CIN + oc0];
#pragma unroll 1
        for (int i = t; i < 576; i += 256) {
            int row = i >> 3, seg = i & 7;
            cpa16(wd + (unsigned)(row*32 + seg*4)*4,
                  wsrc + (size_t)row*CIN + seg*4);
        }
        CP_COMMIT();
    };

    issue(0, 0);
    issue(1, 1);
#pragma unroll 1
    for (int c = 0; c < 64; ++c) {
        if (c < 63) { CP_WAIT(1); }
        else        { CP_WAIT(0); }
        __syncthreads();
        if (c + 2 < 64) issue(c + 2, (c + 2) % 3);

        const int b = c % 3;
        const float* xsb = xs + b * XS_ELEMS;
        const float* wsb = ws + b * WS2;
        unsigned long long c2[16];
#pragma unroll
        for (int i = 0; i < 16; ++i) c2[i] = 0ull;

#pragma unroll 1
        for (int ic = 0; ic < 8; ++ic) {
#pragma unroll
            for (int dy = 0; dy < 3; ++dy) {
                const float* rb = &xsb[ic*XS_IC + (py + dy)*XS_STRIDE + px0];
                float4 a4 = *reinterpret_cast<const float4*>(rb);
                float4 b4 = *reinterpret_cast<const float4*>(rb + 4);
                float2 cc = *reinterpret_cast<const float2*>(rb + 8);
                unsigned long long xr[10];
                PACK2(xr[0], a4.x); PACK2(xr[1], a4.y);
                PACK2(xr[2], a4.z); PACK2(xr[3], a4.w);
                PACK2(xr[4], b4.x); PACK2(xr[5], b4.y);
                PACK2(xr[6], b4.z); PACK2(xr[7], b4.w);
                PACK2(xr[8], cc.x); PACK2(xr[9], cc.y);
#pragma unroll
                for (int dx = 0; dx < 3; ++dx) {
                    const ulonglong2 wv = *reinterpret_cast<const ulonglong2*>(
                        &wsb[(ic*9 + dy*3 + dx)*32 + ocg*4]);
#pragma unroll
                    for (int p = 0; p < 8; ++p) {
                        FMA2(c2[p],     xr[dx + p], wv.x, c2[p]);
                        FMA2(c2[8 + p], xr[dx + p], wv.y, c2[8 + p]);
                    }
                }
            }
        }
#pragma unroll
        for (int i = 0; i < 16; ++i) ADD2(acc2[i], acc2[i], c2[i]);
    }

    const int gy = ty0 + py, gx = tx0 + px0;
    const int ocb = oc0 + ocg*4;
#pragma unroll
    for (int p = 0; p < 2; ++p) {
        float lo[8], hi[8];
#pragma unroll
        for (int q = 0; q < 8; ++q) UNPACK2(lo[q], hi[q], acc2[p*8 + q]);
        float bL = __ldg(&bias[ocb + 2*p]);
        float bH = __ldg(&bias[ocb + 2*p + 1]);
        float* outL = &g_feat[(((size_t)n*CIN + ocb + 2*p) << 12) + (gy << 6) + gx];
        float* outH = &g_feat[(((size_t)n*CIN + ocb + 2*p + 1) << 12) + (gy << 6) + gx];
        reinterpret_cast<float4*>(outL)[0] = make_float4(
            fmaxf(lo[0]+bL,0.f), fmaxf(lo[1]+bL,0.f), fmaxf(lo[2]+bL,0.f), fmaxf(lo[3]+bL,0.f));
        reinterpret_cast<float4*>(outL)[1] = make_float4(
            fmaxf(lo[4]+bL,0.f), fmaxf(lo[5]+bL,0.f), fmaxf(lo[6]+bL,0.f), fmaxf(lo[7]+bL,0.f));
        reinterpret_cast<float4*>(outH)[0] = make_float4(
            fmaxf(hi[0]+bH,0.f), fmaxf(hi[1]+bH,0.f), fmaxf(hi[2]+bH,0.f), fmaxf(hi[3]+bH,0.f));
        reinterpret_cast<float4*>(outH)[1] = make_float4(
            fmaxf(hi[4]+bH,0.f), fmaxf(hi[5]+bH,0.f), fmaxf(hi[6]+bH,0.f), fmaxf(hi[7]+bH,0.f));
    }
}

// ---------------- heads (1x1 convs) + proposal prep ----------------
// Spill fix: per icb the 28 accumulators are processed in two halves of 14
// (fv re-loaded per half, L1-hot). Per-accumulator op order identical.
__global__ void __launch_bounds__(256, 2) heads_proposal(
    const float* __restrict__ sw, const float* __restrict__ sb,
    const float* __restrict__ lw, const float* __restrict__ lb,
    const int* __restrict__ imh, const int* __restrict__ imw,
    float* __restrict__ out)
{
    __shared__ float ws[128][56];
    __shared__ float s_pw[9], s_ph[9];
    const int n = blockIdx.y;
    const int p = blockIdx.x * 256 + threadIdx.x;

    unsigned long long acc2[28];
#pragma unroll
    for (int i = 0; i < 28; ++i) acc2[i] = 0ull;

    if (threadIdx.x < 9) {
        int a = threadIdx.x;
        double r = (a/3 == 0) ? 0.5 : ((a/3 == 1) ? 1.0 : 2.0);
        double s = (a%3 == 0) ? 8.0 : ((a%3 == 1) ? 16.0 : 32.0);
        double hh = (16.0 * s) * sqrt(r);
        double wd = (16.0 * s) * sqrt(1.0 / r);
        s_pw[a] = (float)(wd / 2.0);
        s_ph[a] = (float)(hh / 2.0);
    }

#pragma unroll 1
    for (int c0 = 0; c0 < CIN; c0 += 128) {
        __syncthreads();
        for (int idx = threadIdx.x; idx < 54*128; idx += 256) {
            int c = idx >> 7, ic = idx & 127;
            ws[ic][c] = (c < 18) ? sw[c*CIN + c0 + ic] : lw[(c-18)*CIN + c0 + ic];
        }
        __syncthreads();
#pragma unroll 1
        for (int icb = 0; icb < 4; ++icb) {
#pragma unroll 1
            for (int h = 0; h < 2; ++h) {
                unsigned long long accb2[14];
#pragma unroll
                for (int i = 0; i < 14; ++i) accb2[i] = 0ull;
#pragma unroll 4
                for (int ic2 = 0; ic2 < 32; ++ic2) {
                    int ic = icb*32 + ic2;
                    float fv = __ldg(&g_feat[(((size_t)n*CIN + c0 + ic) << 12) + p]);
                    unsigned long long fv2; PACK2(fv2, fv);
                    const ulonglong2* wr =
                        reinterpret_cast<const ulonglong2*>(&ws[ic][0]);
#pragma unroll
                    for (int q = 0; q < 7; ++q) {
                        ulonglong2 wv = wr[h*7 + q];
                        FMA2(accb2[q*2+0], fv2, wv.x, accb2[q*2+0]);
                        FMA2(accb2[q*2+1], fv2, wv.y, accb2[q*2+1]);
                    }
                }
#pragma unroll
                for (int i = 0; i < 14; ++i)
                    ADD2(acc2[h*14 + i], acc2[h*14 + i], accb2[i]);
            }
        }
    }
    __syncthreads();

    float acc[56];
#pragma unroll
    for (int j = 0; j < 28; ++j) UNPACK2(acc[2*j], acc[2*j+1], acc2[j]);

    int ihv = imh[0], iwv = imw[0];
    float ihf = (ihv > 0 && ihv < 100000) ? (float)ihv : __int_as_float(ihv);
    float iwf = (iwv > 0 && iwv < 100000) ? (float)iwv : __int_as_float(iwv);

    const int yq = p >> 6, xq = p & 63;
    const float sxf = (float)(xq * 16), syf = (float)(yq * 16);

#pragma unroll 1
    for (int a = 0; a < NA; ++a) {
        size_t j = (size_t)p * NA + a;
        float s0 = acc[2*a]   + __ldg(&sb[2*a]);
        float s1 = acc[2*a+1] + __ldg(&sb[2*a+1]);
        out[OFF_SCORES + ((size_t)n*NANCH + j)*2 + 0] = s0;
        out[OFF_SCORES + ((size_t)n*NANCH + j)*2 + 1] = s1;
        float m  = fmaxf(s0, s1);
        float e0 = (float)exp((double)(s0 - m));
        float e1 = (float)exp((double)(s1 - m));
        float fg = e1 / (e0 + e1);

        float dx = acc[18 + 4*a + 0] + __ldg(&lb[4*a + 0]);
        float dy = acc[18 + 4*a + 1] + __ldg(&lb[4*a + 1]);
        float dw = acc[18 + 4*a + 2] + __ldg(&lb[4*a + 2]);
        float dh = acc[18 + 4*a + 3] + __ldg(&lb[4*a + 3]);
        out[OFF_LOCS + ((size_t)n*NANCH + j)*4 + 0] = dx;
        out[OFF_LOCS + ((size_t)n*NANCH + j)*4 + 1] = dy;
        out[OFF_LOCS + ((size_t)n*NANCH + j)*4 + 2] = dw;
        out[OFF_LOCS + ((size_t)n*NANCH + j)*4 + 3] = dh;

        float pw = s_pw[a], ph = s_ph[a];
        float ax1 = sxf - pw, ay1 = syf - ph;
        float ax2 = sxf + pw, ay2 = syf + ph;
        if (n == 0) {
            out[OFF_ANCH + j*4 + 0] = ax1;
            out[OFF_ANCH + j*4 + 1] = ay1;
            out[OFF_ANCH + j*4 + 2] = ax2;
            out[OFF_ANCH + j*4 + 3] = ay2;
        }
        float aw  = ax2 - ax1, ah = ay2 - ay1;
        float acx = ax1 + 0.5f*aw, acy = ay1 + 0.5f*ah;
        float cx  = dx*aw + acx, cy = dy*ah + acy;
        float ew  = (float)exp((double)dw);
        float eh  = (float)exp((double)dh);
        float bw  = ew*aw, bh = eh*ah;
        float x1 = cx - 0.5f*bw, x2 = cx + 0.5f*bw;
        float y1 = cy - 0.5f*bh, y2 = cy + 0.5f*bh;
        x1 = fminf(fmaxf(x1, 0.f), iwf); x2 = fminf(fmaxf(x2, 0.f), iwf);
        y1 = fminf(fmaxf(y1, 0.f), ihf); y2 = fminf(fmaxf(y2, 0.f), ihf);
        bool valid = (x2 - x1 >= 16.f) && (y2 - y1 >= 16.f);
        g_roi[(size_t)n*NANCH + j] = make_float4(x1, y1, x2, y2);
        unsigned int sk = valid ? (__float_as_uint(fg) | 0x80000000u) : 0x007FFFFFu;
        g_keys[((size_t)n << 16) + j] =
            ((unsigned long long)sk << 32) | (unsigned long long)(0xFFFFFFFFu - (unsigned int)j);
    }
}

// ---------------- sorting: 9 real blocks/image + bitonic top-k merges -----
// sort each of the 9 data blocks per image fully DESCENDING
__global__ void __launch_bounds__(256) sort_local_full() {
    __shared__ unsigned long long s[4096];
    const int n   = blockIdx.x / 9;
    const int blk = blockIdx.x - n*9;
    const size_t base = ((size_t)n << 16) + (size_t)blk*4096;
    for (int i = threadIdx.x; i < 4096; i += 256) s[i] = g_keys[base + i];
    __syncthreads();
    for (int k = 2; k <= 4096; k <<= 1) {
        for (int j = k >> 1; j > 0; j >>= 1) {
            for (int t = threadIdx.x; t < 2048; t += 256) {
                int i = ((t & ~(j-1)) << 1) | (t & (j-1));
                bool desc = ((i & k) == 0);
                unsigned long long a = s[i], b = s[i | j];
                if ((a < b) == desc) { s[i] = b; s[i | j] = a; }
            }
            __syncthreads();
        }
    }
    for (int i = threadIdx.x; i < 4096; i += 256) g_keys[base + i] = s[i];
}

// merge blocks (b, b+stride) -> b, keeping the top 4096 of the union, desc.
__global__ void __launch_bounds__(256) merge_topk(int stride, int mper) {
    __shared__ unsigned long long s[4096];
    const int n = blockIdx.x / mper;
    const int m = blockIdx.x % mper;
    unsigned long long* A = g_keys + (((size_t)n << 16) + (size_t)(m*2*stride)*4096);
    const unsigned long long* B = A + (size_t)stride*4096;
    for (int i = threadIdx.x; i < 4096; i += 256) {
        unsigned long long a = A[i], b = B[4095 - i];
        s[i] = a > b ? a : b;
    }
    __syncthreads();
    for (int j = 2048; j > 0; j >>= 1) {
        for (int t = threadIdx.x; t < 2048; t += 256) {
            int i = ((t & ~(j-1)) << 1) | (t & (j-1));
            unsigned long long a = s[i], b = s[i | j];
            if (a < b) { s[i] = b; s[i | j] = a; }
        }
        __syncthreads();
    }
    for (int i = threadIdx.x; i < 4096; i += 256) A[i] = s[i];
}

// ---------------- NMS ----------------
__global__ void gather_top(float* __restrict__ out) {
    const int n = blockIdx.x;
    __shared__ unsigned char sval[3008];
    for (int i = threadIdx.x; i < 3008; i += 128) {
        unsigned long long kk = g_keys[((size_t)n << 16) + i];
        unsigned int sk = (unsigned int)(kk >> 32);
        bool valid = (i < NPRE) && (sk > 0x007FFFFFu);
        float4 bx = make_float4(0.f, 0.f, 0.f, 0.f);
        if (valid) {
            unsigned int j = 0xFFFFFFFFu - (unsigned int)kk;
            bx = g_roi[(size_t)n*NANCH + j];
        }
        g_topbox[(size_t)n*3008 + i] = bx;
        sval[i] = valid ? 1 : 0;
    }
    // roi_indices for this image (folded-in write_misc)
    for (int i = threadIdx.x; i < NPOST; i += 128)
        out[OFF_RIDX + (size_t)n*NPOST + i] = (float)n;
    __syncthreads();
    for (int w = threadIdx.x; w < WPR; w += 128) {
        unsigned long long m = 0ull;
        for (int b = 0; b < 64; ++b) {
            int i = w*64 + b;
            if (i < 3008 && sval[i]) m |= (1ull << b);
        }
        g_vmask[(size_t)n*WPR + w] = m;
    }
}

__global__ void __launch_bounds__(256) build_mask() {
    __shared__ float4 sb[NPRE];
    const int n  = blockIdx.y;
    const int r0 = blockIdx.x * 64;
    for (int i = threadIdx.x; i < NPRE; i += 256) sb[i] = g_topbox[(size_t)n*3008 + i];
    __syncthreads();
    for (int t = threadIdx.x; t < 64*WPR; t += 256) {
        int r = r0 + t / WPR;
        int wj = t % WPR;
        if (r >= NPRE) continue;
        if (wj*64 + 63 <= r) {            // word entirely on/below diagonal
            g_mask[((size_t)n*NPRE + r)*WPR + wj] = 0ull;
            continue;
        }
        float4 a = sb[r];
        float ar = (a.z - a.x) * (a.w - a.y);
        unsigned long long m = 0ull;
#pragma unroll 4
        for (int b = 0; b < 64; ++b) {
            int j = wj*64 + b;
            if (j >= NPRE || j <= r) continue;
            float4 c = sb[j];
            float xx1 = fmaxf(a.x, c.x), yy1 = fmaxf(a.y, c.y);
            float xx2 = fminf(a.z, c.z), yy2 = fminf(a.w, c.w);
            float inter = fmaxf(xx2 - xx1, 0.f) * fmaxf(yy2 - yy1, 0.f);
            float ac = (c.z - c.x) * (c.w - c.y);
            float iou = inter / (ar + ac - inter + 1e-10f);
            if (iou > 0.7f) m |= (1ull << b);
        }
        g_mask[((size_t)n*NPRE + r)*WPR + wj] = m;
    }
}

// 256 threads per image: warp 0 scans the current 64-row chunk from smem
// while warps 1..7 prefetch the next chunk.
__global__ void __launch_bounds__(256) nms_scan(float* __restrict__ out) {
    const int n = blockIdx.x;
    const int t = threadIdx.x;
    const int lane = t & 31, wid = t >> 5;
    __shared__ unsigned long long sbuf[2][64*WPR];
    const unsigned long long* mbase = &g_mask[(size_t)n*NPRE*WPR];
    const float* tb = (const float*)g_topbox;
    float* orow = out + OFF_ROIS + (size_t)n*NPOST*4;

    for (int idx = t; idx < 64*WPR; idx += 256)
        sbuf[0][idx] = mbase[idx];
    __syncthreads();

    unsigned long long R0 = 0ull, R1 = ~0ull;
    int cnt = 0;
    if (wid == 0) {
        R0 = ~g_vmask[(size_t)n*WPR + lane];
        R1 = (lane < 15) ? ~g_vmask[(size_t)n*WPR + 32 + lane] : ~0ull;
    }
    for (int c = 0; c < 47; ++c) {
        const int b = c & 1;
        if (wid > 0 && c + 1 < 47) {
            int r0n = (c + 1) * 64;
            int nrn = min(64, NPRE - r0n);
            for (int idx = t - 32; idx < nrn*WPR; idx += 224)
                sbuf[b ^ 1][idx] = mbase[(size_t)r0n*WPR + idx];
        }
        if (wid == 0) {
            int r0 = c * 64;
            int nr = min(64, NPRE - r0);
            for (int ii = 0; ii < nr; ++ii) {
                int i = r0 + ii;
                unsigned long long m0 = sbuf[b][ii*WPR + lane];
                unsigned long long m1 = (lane < 15) ? sbuf[b][ii*WPR + 32 + lane] : 0ull;
                int w = i >> 6, bb = i & 63;
                unsigned long long own = (w < 32) ? R0 : R1;
                unsigned long long v = __shfl_sync(0xFFFFFFFFu, own, w & 31);
                if (!((v >> bb) & 1ull)) {
                    R0 |= m0; R1 |= m1;
                    if (cnt < NPOST && lane < 4)
                        orow[(size_t)cnt*4 + lane] = tb[((size_t)n*3008 + i)*4 + lane];
                    ++cnt;
                }
            }
        }
        __syncthreads();
    }
    if (wid == 0)
        for (int z = cnt*4 + lane; z < NPOST*4; z += 32) orow[z] = 0.f;
}

// ---------------- launch ----------------
extern "C" void kernel_launch(void* const* d_in, const int* in_sizes, int n_in,
                              void* d_out, int out_size)
{
    const float* x   = (const float*)d_in[0];
    const int*   imh = (const int*)d_in[1];
    const int*   imw = (const int*)d_in[2];
    const float* w1  = (const float*)d_in[3];
    const float* b1  = (const float*)d_in[4];
    const float* sw  = (const float*)d_in[5];
    const float* sbp = (const float*)d_in[6];
    const float* lw  = (const float*)d_in[7];
    const float* lbp = (const float*)d_in[8];
    float* out = (float*)d_out;

    static int smem_set = 0;
    if (!smem_set) {
        cudaFuncSetAttribute(conv3x3_relu,
            cudaFuncAttributeMaxDynamicSharedMemorySize, CONV_SMEM);
        smem_set = 1;
    }

    // heads stays at launch idx 3 (profiler window) to verify the spill fix
    pad_input<<<(int)(((size_t)NB*CIN*XPLANE + 255)/256), 256>>>(x);
    transpose_w<<<(CIN*9*CIN + 255)/256, 256>>>(w1);
    conv3x3_relu<<<dim3(16, 16, 8), 256, CONV_SMEM>>>(b1);
    heads_proposal<<<dim3(16, 8), 256>>>(sw, sbp, lw, lbp, imh, imw, out);
    sort_local_full<<<72, 256>>>();          // 9 real blocks per image
    merge_topk<<<32, 256>>>(1, 4);           // (0,1)(2,3)(4,5)(6,7)
    merge_topk<<<16, 256>>>(2, 2);           // (0,2)(4,6)
    merge_topk<<< 8, 256>>>(4, 1);           // (0,4)
    merge_topk<<< 8, 256>>>(8, 1);           // (0,8) -> block 0 = top 4096
    gather_top<<<8, 128>>>(out);
    build_mask<<<dim3(47, 8), 256>>>();
    nms_scan<<<8, 256>>>(out);
}

// round 16
// speedup vs baseline: 1.0128x; 1.0128x over previous
#include <cuda_runtime.h>
#include <math.h>

// ---------------- problem constants ----------------
#define NB     8
#define CIN    512
#define HH     64
#define WW     64
#define NPOS   4096              // 64*64
#define NA     9
#define NANCH  36864             // 4096*9 = 9 blocks of 4096
#define NSORT  65536             // per-image key stride (only blocks 0..8 used)
#define NPRE   3000
#define NPOST  600
#define WPR    47                // words per NMS mask row: ceil(3008/64)
#define NPAD   68                // padded row stride (272B = 16B-aligned rows)
#define XPLANE (NPAD*NPAD)       // 4624

// output layout (floats)
#define OFF_LOCS   ((size_t)0)
#define OFF_SCORES ((size_t)(NB*NANCH*4))                      // 1,179,648
#define OFF_ROIS   (OFF_SCORES + (size_t)(NB*NANCH*2))         // 1,769,472
#define OFF_RIDX   (OFF_ROIS + (size_t)(NB*NPOST*4))           // 1,788,672
#define OFF_ANCH   (OFF_RIDX + (size_t)(NB*NPOST))             // 1,793,472

// ---------------- static scratch ----------------
__device__ float               g_feat[(size_t)NB*CIN*NPOS];        // 64 MiB
__device__ float               g_xpad[(size_t)NB*CIN*XPLANE];      // 75 MiB padded input
__device__ float               g_wt[(size_t)CIN*9*CIN];            // transposed weights [ic*9+kk][oc]
__device__ float4              g_roi[(size_t)NB*NANCH];            // clipped rois
__device__ unsigned long long  g_keys[(size_t)NB*NSORT];           // sort keys
__device__ float4              g_topbox[(size_t)NB*3008];
__device__ unsigned long long  g_vmask[(size_t)NB*WPR];
__device__ unsigned long long  g_mask[(size_t)NB*NPRE*WPR];        // 9 MiB

// ---------------- packed f32x2 helpers ----------------
#define FMA2(d, a, b, c) \
    asm("fma.rn.f32x2 %0, %1, %2, %3;" : "=l"(d) : "l"(a), "l"(b), "l"(c))
#define ADD2(d, a, b) \
    asm("add.rn.f32x2 %0, %1, %2;" : "=l"(d) : "l"(a), "l"(b))
#define PACK2(d, f) \
    asm("mov.b64 %0, {%1, %1};" : "=l"(d) : "f"(f))
#define UNPACK2(lo, hi, v) \
    asm("mov.b64 {%0, %1}, %2;" : "=f"(lo), "=f"(hi) : "l"(v))

// ---------------- cp.async helpers ----------------
__device__ __forceinline__ unsigned int smem_u32(const void* p) {
    return (unsigned int)__cvta_generic_to_shared(p);
}
__device__ __forceinline__ void cpa16(unsigned int dst, const float* src) {
    asm volatile("cp.async.cg.shared.global [%0], [%1], 16;" :: "r"(dst), "l"(src));
}
#define CP_COMMIT() asm volatile("cp.async.commit_group;" ::: "memory")
#define CP_WAIT(n)  asm volatile("cp.async.wait_group %0;" :: "n"(n) : "memory")

// ---------------- prep: pad input, transpose weights ----------------
__global__ void pad_input(const float* __restrict__ x) {
    long long i = (long long)blockIdx.x * blockDim.x + threadIdx.x;
    if (i >= (long long)NB*CIN*XPLANE) return;
    int pos = (int)(i % XPLANE);
    long long plane = i / XPLANE;                  // n*CIN+ic
    int yy = pos / NPAD, xx = pos - yy*NPAD;
    float v = 0.f;
    if (yy >= 1 && yy <= 64 && xx >= 1 && xx <= 64)
        v = x[(plane << 12) + ((yy-1) << 6) + (xx-1)];
    g_xpad[i] = v;
}

__global__ void transpose_w(const float* __restrict__ w) {
    int i = blockIdx.x * blockDim.x + threadIdx.x;   // CIN*9*CIN = 2359296
    if (i >= CIN*9*CIN) return;
    int oc = i & 511;
    int row = i >> 9;                                 // ic*9+kk
    int ic = row / 9, kk = row - ic*9;
    g_wt[i] = w[((size_t)oc*CIN + ic)*9 + kk];
}

// ---------------- conv 3x3 + relu (8 px x 4 oc, 3-stage pipeline) ---------
#define XS_STRIDE 20           // padded row stride (16B alignment for LDS.128)
#define XS_IC     360          // 18*20
#define XS_ELEMS  2880         // 8*360
#define WS2       2304         // 72*32
#define CONV_SMEM (3*(XS_ELEMS+WS2)*4)
__global__ void __launch_bounds__(256, 2) conv3x3_relu(
    const float* __restrict__ bias)
{
    extern __shared__ float smem[];
    float* xs = smem;                       // [3][2880]
    float* ws = smem + 3*XS_ELEMS;          // [3][2304]
    const int tile = blockIdx.x;
    const int oc0  = blockIdx.y * 32;
    const int n    = blockIdx.z;
    const int tx0  = (tile & 3) * 16, ty0 = (tile >> 2) * 16;
    const int t    = threadIdx.x;
    const int ocg  = t >> 5;               // 0..7 -> 4 oc each
    const int pid  = t & 31;
    const int px0  = (pid & 1) * 8;        // 0,8
    const int py   = pid >> 1;             // 0..15

    const float* xbase = &g_xpad[((size_t)n*CIN) * XPLANE + (size_t)ty0*NPAD + tx0];
    const unsigned int xs_a = smem_u32(xs);
    const unsigned int ws_a = smem_u32(ws);

    unsigned long long acc2[16];           // [oc_pair 0..1][px 0..7]
#pragma unroll
    for (int i = 0; i < 16; ++i) acc2[i] = 0ull;

    auto issue = [&](int c, int b) {
        const int ic0 = c * 8;
        unsigned int xd = xs_a + (unsigned)b * (XS_ELEMS*4);
        const float* xsrc = xbase + (size_t)ic0 * XPLANE;
#pragma unroll 1
        for (int i = t; i < 720; i += 256) {
            int ic = i / 90, r = i - ic*90;
            int yy = r / 5, seg = r - yy*5;
            cpa16(xd + (unsigned)(ic*XS_IC + yy*XS_STRIDE + seg*4)*4,
                  xsrc + (size_t)ic*XPLANE + yy*NPAD + seg*4);
        }
        unsigned int wd = ws_a + (unsigned)b * (WS2*4);
        const float* wsrc = &g_wt[(size_t)(ic0*9) * CIN + oc0];
#pragma unroll 1
        for (int i = t; i < 576; i += 256) {
            int row = i >> 3, seg = i & 7;
            cpa16(wd + (unsigned)(row*32 + seg*4)*4,
                  wsrc + (size_t)row*CIN + seg*4);
        }
        CP_COMMIT();
    };

    issue(0, 0);
    issue(1, 1);
#pragma unroll 1
    for (int c = 0; c < 64; ++c) {
        if (c < 63) { CP_WAIT(1); }
        else        { CP_WAIT(0); }
        __syncthreads();
        if (c + 2 < 64) issue(c + 2, (c + 2) % 3);

        const int b = c % 3;
        const float* xsb = xs + b * XS_ELEMS;
        const float* wsb = ws + b * WS2;
        unsigned long long c2[16];
#pragma unroll
        for (int i = 0; i < 16; ++i) c2[i] = 0ull;

#pragma unroll 1
        for (int ic = 0; ic < 8; ++ic) {
#pragma unroll
            for (int dy = 0; dy < 3; ++dy) {
                const float* rb = &xsb[ic*XS_IC + (py + dy)*XS_STRIDE + px0];
                float4 a4 = *reinterpret_cast<const float4*>(rb);
                float4 b4 = *reinterpret_cast<const float4*>(rb + 4);
                float2 cc = *reinterpret_cast<const float2*>(rb + 8);
                unsigned long long xr[10];
                PACK2(xr[0], a4.x); PACK2(xr[1], a4.y);
                PACK2(xr[2], a4.z); PACK2(xr[3], a4.w);
                PACK2(xr[4], b4.x); PACK2(xr[5], b4.y);
                PACK2(xr[6], b4.z); PACK2(xr[7], b4.w);
                PACK2(xr[8], cc.x); PACK2(xr[9], cc.y);
#pragma unroll
                for (int dx = 0; dx < 3; ++dx) {
                    const ulonglong2 wv = *reinterpret_cast<const ulonglong2*>(
                        &wsb[(ic*9 + dy*3 + dx)*32 + ocg*4]);
#pragma unroll
                    for (int p = 0; p < 8; ++p) {
                        FMA2(c2[p],     xr[dx + p], wv.x, c2[p]);
                        FMA2(c2[8 + p], xr[dx + p], wv.y, c2[8 + p]);
                    }
                }
            }
        }
#pragma unroll
        for (int i = 0; i < 16; ++i) ADD2(acc2[i], acc2[i], c2[i]);
    }

    const int gy = ty0 + py, gx = tx0 + px0;
    const int ocb = oc0 + ocg*4;
#pragma unroll
    for (int p = 0; p < 2; ++p) {
        float lo[8], hi[8];
#pragma unroll
        for (int q = 0; q < 8; ++q) UNPACK2(lo[q], hi[q], acc2[p*8 + q]);
        float bL = __ldg(&bias[ocb + 2*p]);
        float bH = __ldg(&bias[ocb + 2*p + 1]);
        float* outL = &g_feat[(((size_t)n*CIN + ocb + 2*p) << 12) + (gy << 6) + gx];
        float* outH = &g_feat[(((size_t)n*CIN + ocb + 2*p + 1) << 12) + (gy << 6) + gx];
        reinterpret_cast<float4*>(outL)[0] = make_float4(
            fmaxf(lo[0]+bL,0.f), fmaxf(lo[1]+bL,0.f), fmaxf(lo[2]+bL,0.f), fmaxf(lo[3]+bL,0.f));
        reinterpret_cast<float4*>(outL)[1] = make_float4(
            fmaxf(lo[4]+bL,0.f), fmaxf(lo[5]+bL,0.f), fmaxf(lo[6]+bL,0.f), fmaxf(lo[7]+bL,0.f));
        reinterpret_cast<float4*>(outH)[0] = make_float4(
            fmaxf(hi[0]+bH,0.f), fmaxf(hi[1]+bH,0.f), fmaxf(hi[2]+bH,0.f), fmaxf(hi[3]+bH,0.f));
        reinterpret_cast<float4*>(outH)[1] = make_float4(
            fmaxf(hi[4]+bH,0.f), fmaxf(hi[5]+bH,0.f), fmaxf(hi[6]+bH,0.f), fmaxf(hi[7]+bH,0.f));
    }
}

// ---------------- heads (1x1 convs) + proposal prep ----------------
// Round-14 single-pass inner loop (1 LDG per ic) with a finer launch:
// grid (32, 8) x 128 threads, __launch_bounds__(128, 2) -> up to 256 regs,
// no spills, all 148 SMs covered. Per-thread op sequence identical.
__global__ void __launch_bounds__(128, 2) heads_proposal(
    const float* __restrict__ sw, const float* __restrict__ sb,
    const float* __restrict__ lw, const float* __restrict__ lb,
    const int* __restrict__ imh, const int* __restrict__ imw,
    float* __restrict__ out)
{
    __shared__ float ws[128][56];
    __shared__ float s_pw[9], s_ph[9];
    const int n = blockIdx.y;
    const int p = blockIdx.x * 128 + threadIdx.x;

    unsigned long long acc2[28], accb2[28];
#pragma unroll
    for (int i = 0; i < 28; ++i) acc2[i] = 0ull;

    if (threadIdx.x < 9) {
        int a = threadIdx.x;
        double r = (a/3 == 0) ? 0.5 : ((a/3 == 1) ? 1.0 : 2.0);
        double s = (a%3 == 0) ? 8.0 : ((a%3 == 1) ? 16.0 : 32.0);
        double hh = (16.0 * s) * sqrt(r);
        double wd = (16.0 * s) * sqrt(1.0 / r);
        s_pw[a] = (float)(wd / 2.0);
        s_ph[a] = (float)(hh / 2.0);
    }

#pragma unroll 1
    for (int c0 = 0; c0 < CIN; c0 += 128) {
        __syncthreads();
        for (int idx = threadIdx.x; idx < 54*128; idx += 128) {
            int c = idx >> 7, ic = idx & 127;
            ws[ic][c] = (c < 18) ? sw[c*CIN + c0 + ic] : lw[(c-18)*CIN + c0 + ic];
        }
        __syncthreads();
#pragma unroll 1
        for (int icb = 0; icb < 4; ++icb) {
#pragma unroll
            for (int i = 0; i < 28; ++i) accb2[i] = 0ull;
#pragma unroll 4
            for (int ic2 = 0; ic2 < 32; ++ic2) {
                int ic = icb*32 + ic2;
                float fv = __ldg(&g_feat[(((size_t)n*CIN + c0 + ic) << 12) + p]);
                unsigned long long fv2; PACK2(fv2, fv);
                const ulonglong2* wr = reinterpret_cast<const ulonglong2*>(&ws[ic][0]);
#pragma unroll
                for (int q = 0; q < 14; ++q) {
                    ulonglong2 wv = wr[q];
                    FMA2(accb2[q*2+0], fv2, wv.x, accb2[q*2+0]);
                    FMA2(accb2[q*2+1], fv2, wv.y, accb2[q*2+1]);
                }
            }
#pragma unroll
            for (int i = 0; i < 28; ++i) ADD2(acc2[i], acc2[i], accb2[i]);
        }
    }
    __syncthreads();

    float acc[56];
#pragma unroll
    for (int j = 0; j < 28; ++j) UNPACK2(acc[2*j], acc[2*j+1], acc2[j]);

    int ihv = imh[0], iwv = imw[0];
    float ihf = (ihv > 0 && ihv < 100000) ? (float)ihv : __int_as_float(ihv);
    float iwf = (iwv > 0 && iwv < 100000) ? (float)iwv : __int_as_float(iwv);

    const int yq = p >> 6, xq = p & 63;
    const float sxf = (float)(xq * 16), syf = (float)(yq * 16);

#pragma unroll 1
    for (int a = 0; a < NA; ++a) {
        size_t j = (size_t)p * NA + a;
        float s0 = acc[2*a]   + __ldg(&sb[2*a]);
        float s1 = acc[2*a+1] + __ldg(&sb[2*a+1]);
        out[OFF_SCORES + ((size_t)n*NANCH + j)*2 + 0] = s0;
        out[OFF_SCORES + ((size_t)n*NANCH + j)*2 + 1] = s1;
        float m  = fmaxf(s0, s1);
        float e0 = (float)exp((double)(s0 - m));
        float e1 = (float)exp((double)(s1 - m));
        float fg = e1 / (e0 + e1);

        float dx = acc[18 + 4*a + 0] + __ldg(&lb[4*a + 0]);
        float dy = acc[18 + 4*a + 1] + __ldg(&lb[4*a + 1]);
        float dw = acc[18 + 4*a + 2] + __ldg(&lb[4*a + 2]);
        float dh = acc[18 + 4*a + 3] + __ldg(&lb[4*a + 3]);
        out[OFF_LOCS + ((size_t)n*NANCH + j)*4 + 0] = dx;
        out[OFF_LOCS + ((size_t)n*NANCH + j)*4 + 1] = dy;
        out[OFF_LOCS + ((size_t)n*NANCH + j)*4 + 2] = dw;
        out[OFF_LOCS + ((size_t)n*NANCH + j)*4 + 3] = dh;

        float pw = s_pw[a], ph = s_ph[a];
        float ax1 = sxf - pw, ay1 = syf - ph;
        float ax2 = sxf + pw, ay2 = syf + ph;
        if (n == 0) {
            out[OFF_ANCH + j*4 + 0] = ax1;
            out[OFF_ANCH + j*4 + 1] = ay1;
            out[OFF_ANCH + j*4 + 2] = ax2;
            out[OFF_ANCH + j*4 + 3] = ay2;
        }
        float aw  = ax2 - ax1, ah = ay2 - ay1;
        float acx = ax1 + 0.5f*aw, acy = ay1 + 0.5f*ah;
        float cx  = dx*aw + acx, cy = dy*ah + acy;
        float ew  = (float)exp((double)dw);
        float eh  = (float)exp((double)dh);
        float bw  = ew*aw, bh = eh*ah;
        float x1 = cx - 0.5f*bw, x2 = cx + 0.5f*bw;
        float y1 = cy - 0.5f*bh, y2 = cy + 0.5f*bh;
        x1 = fminf(fmaxf(x1, 0.f), iwf); x2 = fminf(fmaxf(x2, 0.f), iwf);
        y1 = fminf(fmaxf(y1, 0.f), ihf); y2 = fminf(fmaxf(y2, 0.f), ihf);
        bool valid = (x2 - x1 >= 16.f) && (y2 - y1 >= 16.f);
        g_roi[(size_t)n*NANCH + j] = make_float4(x1, y1, x2, y2);
        unsigned int sk = valid ? (__float_as_uint(fg) | 0x80000000u) : 0x007FFFFFu;
        g_keys[((size_t)n << 16) + j] =
            ((unsigned long long)sk << 32) | (unsigned long long)(0xFFFFFFFFu - (unsigned int)j);
    }
}

// ---------------- sorting: 9 real blocks/image + bitonic top-k merges -----
__global__ void __launch_bounds__(256) sort_local_full() {
    __shared__ unsigned long long s[4096];
    const int n   = blockIdx.x / 9;
    const int blk = blockIdx.x - n*9;
    const size_t base = ((size_t)n << 16) + (size_t)blk*4096;
    for (int i = threadIdx.x; i < 4096; i += 256) s[i] = g_keys[base + i];
    __syncthreads();
    for (int k = 2; k <= 4096; k <<= 1) {
        for (int j = k >> 1; j > 0; j >>= 1) {
            for (int t = threadIdx.x; t < 2048; t += 256) {
                int i = ((t & ~(j-1)) << 1) | (t & (j-1));
                bool desc = ((i & k) == 0);
                unsigned long long a = s[i], b = s[i | j];
                if ((a < b) == desc) { s[i] = b; s[i | j] = a; }
            }
            __syncthreads();
        }
    }
    for (int i = threadIdx.x; i < 4096; i += 256) g_keys[base + i] = s[i];
}

__global__ void __launch_bounds__(256) merge_topk(int stride, int mper) {
    __shared__ unsigned long long s[4096];
    const int n = blockIdx.x / mper;
    const int m = blockIdx.x % mper;
    unsigned long long* A = g_keys + (((size_t)n << 16) + (size_t)(m*2*stride)*4096);
    const unsigned long long* B = A + (size_t)stride*4096;
    for (int i = threadIdx.x; i < 4096; i += 256) {
        unsigned long long a = A[i], b = B[4095 - i];
        s[i] = a > b ? a : b;
    }
    __syncthreads();
    for (int j = 2048; j > 0; j >>= 1) {
        for (int t = threadIdx.x; t < 2048; t += 256) {
            int i = ((t & ~(j-1)) << 1) | (t & (j-1));
            unsigned long long a = s[i], b = s[i | j];
            if (a < b) { s[i] = b; s[i | j] = a; }
        }
        __syncthreads();
    }
    for (int i = threadIdx.x; i < 4096; i += 256) A[i] = s[i];
}

// ---------------- NMS ----------------
__global__ void gather_top(float* __restrict__ out) {
    const int n = blockIdx.x;
    __shared__ unsigned char sval[3008];
    for (int i = threadIdx.x; i < 3008; i += 128) {
        unsigned long long kk = g_keys[((size_t)n << 16) + i];
        unsigned int sk = (unsigned int)(kk >> 32);
        bool valid = (i < NPRE) && (sk > 0x007FFFFFu);
        float4 bx = make_float4(0.f, 0.f, 0.f, 0.f);
        if (valid) {
            unsigned int j = 0xFFFFFFFFu - (unsigned int)kk;
            bx = g_roi[(size_t)n*NANCH + j];
        }
        g_topbox[(size_t)n*3008 + i] = bx;
        sval[i] = valid ? 1 : 0;
    }
    for (int i = threadIdx.x; i < NPOST; i += 128)
        out[OFF_RIDX + (size_t)n*NPOST + i] = (float)n;
    __syncthreads();
    for (int w = threadIdx.x; w < WPR; w += 128) {
        unsigned long long m = 0ull;
        for (int b = 0; b < 64; ++b) {
            int i = w*64 + b;
            if (i < 3008 && sval[i]) m |= (1ull << b);
        }
        g_vmask[(size_t)n*WPR + w] = m;
    }
}

__global__ void __launch_bounds__(256) build_mask() {
    __shared__ float4 sb[NPRE];
    const int n  = blockIdx.y;
    const int r0 = blockIdx.x * 64;
    for (int i = threadIdx.x; i < NPRE; i += 256) sb[i] = g_topbox[(size_t)n*3008 + i];
    __syncthreads();
    for (int t = threadIdx.x; t < 64*WPR; t += 256) {
        int r = r0 + t / WPR;
        int wj = t % WPR;
        if (r >= NPRE) continue;
        if (wj*64 + 63 <= r) {
            g_mask[((size_t)n*NPRE + r)*WPR + wj] = 0ull;
            continue;
        }
        float4 a = sb[r];
        float ar = (a.z - a.x) * (a.w - a.y);
        unsigned long long m = 0ull;
#pragma unroll 4
        for (int b = 0; b < 64; ++b) {
            int j = wj*64 + b;
            if (j >= NPRE || j <= r) continue;
            float4 c = sb[j];
            float xx1 = fmaxf(a.x, c.x), yy1 = fmaxf(a.y, c.y);
            float xx2 = fminf(a.z, c.z), yy2 = fminf(a.w, c.w);
            float inter = fmaxf(xx2 - xx1, 0.f) * fmaxf(yy2 - yy1, 0.f);
            float ac = (c.z - c.x) * (c.w - c.y);
            float iou = inter / (ar + ac - inter + 1e-10f);
            if (iou > 0.7f) m |= (1ull << b);
        }
        g_mask[((size_t)n*NPRE + r)*WPR + wj] = m;
    }
}

__global__ void __launch_bounds__(256) nms_scan(float* __restrict__ out) {
    const int n = blockIdx.x;
    const int t = threadIdx.x;
    const int lane = t & 31, wid = t >> 5;
    __shared__ unsigned long long sbuf[2][64*WPR];
    const unsigned long long* mbase = &g_mask[(size_t)n*NPRE*WPR];
    const float* tb = (const float*)g_topbox;
    float* orow = out + OFF_ROIS + (size_t)n*NPOST*4;

    for (int idx = t; idx < 64*WPR; idx += 256)
        sbuf[0][idx] = mbase[idx];
    __syncthreads();

    unsigned long long R0 = 0ull, R1 = ~0ull;
    int cnt = 0;
    if (wid == 0) {
        R0 = ~g_vmask[(size_t)n*WPR + lane];
        R1 = (lane < 15) ? ~g_vmask[(size_t)n*WPR + 32 + lane] : ~0ull;
    }
    for (int c = 0; c < 47; ++c) {
        const int b = c & 1;
        if (wid > 0 && c + 1 < 47) {
            int r0n = (c + 1) * 64;
            int nrn = min(64, NPRE - r0n);
            for (int idx = t - 32; idx < nrn*WPR; idx += 224)
                sbuf[b ^ 1][idx] = mbase[(size_t)r0n*WPR + idx];
        }
        if (wid == 0) {
            int r0 = c * 64;
            int nr = min(64, NPRE - r0);
            for (int ii = 0; ii < nr; ++ii) {
                int i = r0 + ii;
                unsigned long long m0 = sbuf[b][ii*WPR + lane];
                unsigned long long m1 = (lane < 15) ? sbuf[b][ii*WPR + 32 + lane] : 0ull;
                int w = i >> 6, bb = i & 63;
                unsigned long long own = (w < 32) ? R0 : R1;
                unsigned long long v = __shfl_sync(0xFFFFFFFFu, own, w & 31);
                if (!((v >> bb) & 1ull)) {
                    R0 |= m0; R1 |= m1;
                    if (cnt < NPOST && lane < 4)
                        orow[(size_t)cnt*4 + lane] = tb[((size_t)n*3008 + i)*4 + lane];
                    ++cnt;
                }
            }
        }
        __syncthreads();
    }
    if (wid == 0)
        for (int z = cnt*4 + lane; z < NPOST*4; z += 32) orow[z] = 0.f;
}

// ---------------- launch ----------------
extern "C" void kernel_launch(void* const* d_in, const int* in_sizes, int n_in,
                              void* d_out, int out_size)
{
    const float* x   = (const float*)d_in[0];
    const int*   imh = (const int*)d_in[1];
    const int*   imw = (const int*)d_in[2];
    const float* w1  = (const float*)d_in[3];
    const float* b1  = (const float*)d_in[4];
    const float* sw  = (const float*)d_in[5];
    const float* sbp = (const float*)d_in[6];
    const float* lw  = (const float*)d_in[7];
    const float* lbp = (const float*)d_in[8];
    float* out = (float*)d_out;

    static int smem_set = 0;
    if (!smem_set) {
        cudaFuncSetAttribute(conv3x3_relu,
            cudaFuncAttributeMaxDynamicSharedMemorySize, CONV_SMEM);
        smem_set = 1;
    }

    // heads at launch idx 3 (profiler window) to verify the reshape
    pad_input<<<(int)(((size_t)NB*CIN*XPLANE + 255)/256), 256>>>(x);
    transpose_w<<<(CIN*9*CIN + 255)/256, 256>>>(w1);
    conv3x3_relu<<<dim3(16, 16, 8), 256, CONV_SMEM>>>(b1);
    heads_proposal<<<dim3(32, 8), 128>>>(sw, sbp, lw, lbp, imh, imw, out);
    sort_local_full<<<72, 256>>>();          // 9 real blocks per image
    merge_topk<<<32, 256>>>(1, 4);           // (0,1)(2,3)(4,5)(6,7)
    merge_topk<<<16, 256>>>(2, 2);           // (0,2)(4,6)
    merge_topk<<< 8, 256>>>(4, 1);           // (0,4)
    merge_topk<<< 8, 256>>>(8, 1);           // (0,8) -> block 0 = top 4096
    gather_top<<<8, 128>>>(out);
    build_mask<<<dim3(47, 8), 256>>>();
    nms_scan<<<8, 256>>>(out);
}